// round 13
// baseline (speedup 1.0000x reference)
#include <cuda_runtime.h>
#include <cuda_fp16.h>
#include <cuda_fp8.h>

// NNUE HalfKP forward, e4m3 combined-table, paired-feature gather.
//
// Stage 1: comb[i][d] = ft_w[i][d] + fft_w[i%640][d]; per-row absmax ->
//   scale (rowmax -> 448); e4m3 encode. 2 rows per warp.
// Stage 2: gather. Two warps per batch element (warp parity = side).
//   Within a warp, lanes 0-15 gather feature 2k, lanes 16-31 feature 2k+1;
//   each lane loads 16B (16 dims) -> one LDG.128 covers TWO feature rows.
//   Halves LDG+LDS issue count vs one-feature-per-warp. Parities merged by
//   one shfl_xor(16) at the end. Batch-4 prefetch keeps 4 LDG.128 in
//   flight. fp16 accumulate, fp32 epilogue with exact fp32 biases.

constexpr int FT_OUT  = 256;
constexpr int NUM_FT  = 40960;
constexpr int NUM_FFT = 640;
constexpr int MAXF    = 32;

__device__ uint2 g_comb [(size_t)NUM_FT * 32];   // 10 MB e4m3 (256B per row)
__device__ float g_scale[NUM_FT];                // per-row dequant scale (m/448)

__device__ __forceinline__ __half2 dec_e4m3x2(unsigned int s) {
    __half2_raw r = __nv_cvt_fp8x2_to_halfraw2((__nv_fp8x2_storage_t)(unsigned short)s, __NV_E4M3);
    return __half2(r);
}

__global__ __launch_bounds__(256) void build_table_kernel(
    const float* __restrict__ ft_w,   // [40960, 256]
    const float* __restrict__ fft_w)  // [640, 256]
{
    const int warp = threadIdx.x >> 5;
    const int lane = threadIdx.x & 31;
    const int row0 = (blockIdx.x * 8 + warp) * 2;

    float4 A[2][2], B[2][2];
#pragma unroll
    for (int r = 0; r < 2; ++r) {
        const int row = row0 + r;
        const float* pf = ft_w  + (size_t)row * FT_OUT + lane * 8;
        const float* pg = fft_w + (size_t)(row % NUM_FFT) * FT_OUT + lane * 8;
        A[r][0] = *reinterpret_cast<const float4*>(pf);
        A[r][1] = *reinterpret_cast<const float4*>(pf + 4);
        B[r][0] = *reinterpret_cast<const float4*>(pg);
        B[r][1] = *reinterpret_cast<const float4*>(pg + 4);
    }

#pragma unroll
    for (int r = 0; r < 2; ++r) {
        const int row = row0 + r;
        float s[8] = { A[r][0].x + B[r][0].x, A[r][0].y + B[r][0].y,
                       A[r][0].z + B[r][0].z, A[r][0].w + B[r][0].w,
                       A[r][1].x + B[r][1].x, A[r][1].y + B[r][1].y,
                       A[r][1].z + B[r][1].z, A[r][1].w + B[r][1].w };

        float m = 0.f;
#pragma unroll
        for (int j = 0; j < 8; ++j) m = fmaxf(m, fabsf(s[j]));
#pragma unroll
        for (int off = 16; off > 0; off >>= 1)
            m = fmaxf(m, __shfl_xor_sync(0xffffffffu, m, off));

        m = fmaxf(m, 1e-20f);
        const float inv = 448.0f / m;

        unsigned short e[4];
#pragma unroll
        for (int j = 0; j < 4; ++j) {
            float2 pr = make_float2(s[2 * j] * inv, s[2 * j + 1] * inv);
            e[j] = (unsigned short)__nv_cvt_float2_to_fp8x2(pr, __NV_SATFINITE, __NV_E4M3);
        }
        uint2 packed;
        packed.x = (unsigned)e[0] | ((unsigned)e[1] << 16);
        packed.y = (unsigned)e[2] | ((unsigned)e[3] << 16);

        g_comb[(size_t)row * 32 + lane] = packed;
        if (lane == 0) g_scale[row] = m * (1.0f / 448.0f);
    }
}

__global__ __launch_bounds__(256) void nnue_halfkp_kernel(
    const float* __restrict__ values,        // [B, 32]
    const int*   __restrict__ stm_indices,   // [B, 32]
    const int*   __restrict__ nstm_indices,  // [B, 32]
    const float* __restrict__ ft_b,          // [256]
    const float* __restrict__ fft_b,         // [256]
    const float* __restrict__ out_w,         // [1, 512]
    const float* __restrict__ out_b,         // [1]
    float*       __restrict__ out,           // [B, 1]
    int batch)
{
    __shared__ float s_dot[8];
    __shared__ uint2 s_pre[8][32];            // per-warp: {row index, vsh bits}

    const int warp = threadIdx.x >> 5;        // 0..7
    const int lane = threadIdx.x & 31;
    const int elem = blockIdx.x * 4 + (warp >> 1);
    const int side = warp & 1;                 // 0 = stm, 1 = nstm
    const int e    = (elem < batch) ? elem : (batch - 1);

    const int* __restrict__ idx = side ? nstm_indices : stm_indices;

    // Preload: lane l prepares feature l -> {row index, value*scale fp16x2}.
    {
        const float v = values[e * MAXF + lane];
        const int   i = idx[e * MAXF + lane];
        const float vs = v * g_scale[i];
        const __half2 vsh = __float2half2_rn(vs);
        uint2 t;
        t.x = (unsigned)i;
        t.y = *reinterpret_cast<const unsigned*>(&vsh);
        s_pre[warp][lane] = t;
    }
    __syncwarp();

    const int fsel    = lane >> 4;     // which feature of the pair this lane serves
    const int sublane = lane & 15;     // 16B chunk within the 256B row

    // This lane's 16B-chunk base: ((uint4*)g_comb) + sublane; row i at +i*16.
    const uint4* __restrict__ lane_base =
        reinterpret_cast<const uint4*>(g_comb) + sublane;

    __half2 acc[8];
#pragma unroll
    for (int k = 0; k < 8; ++k) acc[k] = __float2half2_rn(0.f);

#pragma unroll
    for (int k0 = 0; k0 < MAXF / 2; k0 += 4) {
        // Phase 1: 4 independent LDG.128 (8 features) in flight.
        uint4   p[4];
        __half2 v[4];
#pragma unroll
        for (int j = 0; j < 4; ++j) {
            const uint2 t = s_pre[warp][2 * (k0 + j) + fsel];   // LDS.64, 2-way bcast
            p[j] = lane_base[(size_t)t.x * 16];                 // IMAD.WIDE + LDG.128
            v[j] = *reinterpret_cast<const __half2*>(&t.y);
        }
        // Phase 2: decode + accumulate (16 dims per lane).
#pragma unroll
        for (int j = 0; j < 4; ++j) {
            acc[0] = __hfma2(dec_e4m3x2(p[j].x),       v[j], acc[0]);
            acc[1] = __hfma2(dec_e4m3x2(p[j].x >> 16), v[j], acc[1]);
            acc[2] = __hfma2(dec_e4m3x2(p[j].y),       v[j], acc[2]);
            acc[3] = __hfma2(dec_e4m3x2(p[j].y >> 16), v[j], acc[3]);
            acc[4] = __hfma2(dec_e4m3x2(p[j].z),       v[j], acc[4]);
            acc[5] = __hfma2(dec_e4m3x2(p[j].z >> 16), v[j], acc[5]);
            acc[6] = __hfma2(dec_e4m3x2(p[j].w),       v[j], acc[6]);
            acc[7] = __hfma2(dec_e4m3x2(p[j].w >> 16), v[j], acc[7]);
        }
    }

    // Merge the two feature-parities: lanes l and l^16 hold the same 16 dims.
    float av[16];
#pragma unroll
    for (int k = 0; k < 8; ++k) {
        unsigned int a = *reinterpret_cast<unsigned int*>(&acc[k]);
        unsigned int b = __shfl_xor_sync(0xffffffffu, a, 16);
        const __half2 sum = __hadd2(*reinterpret_cast<__half2*>(&a),
                                    *reinterpret_cast<__half2*>(&b));
        const float2 f = __half22float2(sum);
        av[2 * k]     = f.x;
        av[2 * k + 1] = f.y;
    }

    // Epilogue: this lane owns 16 dims at col = sublane*16 (duplicated per half).
    const int col = sublane * 16;
    const float* w = out_w + side * FT_OUT;

    float dot = 0.f;
#pragma unroll
    for (int q = 0; q < 4; ++q) {
        const float4 fb  = *reinterpret_cast<const float4*>(ft_b  + col + 4 * q);
        const float4 ffb = *reinterpret_cast<const float4*>(fft_b + col + 4 * q);
        const float4 wq  = *reinterpret_cast<const float4*>(w     + col + 4 * q);
        const float b0 = fb.x + ffb.x, b1 = fb.y + ffb.y,
                    b2 = fb.z + ffb.z, b3 = fb.w + ffb.w;
        dot += fminf(fmaxf(av[4 * q]     + b0, 0.f), 1.f) * wq.x;
        dot += fminf(fmaxf(av[4 * q + 1] + b1, 0.f), 1.f) * wq.y;
        dot += fminf(fmaxf(av[4 * q + 2] + b2, 0.f), 1.f) * wq.z;
        dot += fminf(fmaxf(av[4 * q + 3] + b3, 0.f), 1.f) * wq.w;
    }

    // Reduce within each 16-lane half (halves hold identical data).
#pragma unroll
    for (int off = 8; off > 0; off >>= 1)
        dot += __shfl_xor_sync(0xffffffffu, dot, off);

    if (lane == 0) s_dot[warp] = dot;
    __syncthreads();

    if (threadIdx.x < 4) {
        const int eo = blockIdx.x * 4 + threadIdx.x;
        if (eo < batch) {
            const float x = s_dot[2 * threadIdx.x] + s_dot[2 * threadIdx.x + 1] + out_b[0];
            out[eo] = 1.0f / (1.0f + expf(-x));
        }
    }
}

extern "C" void kernel_launch(void* const* d_in, const int* in_sizes, int n_in,
                              void* d_out, int out_size)
{
    const float* values = (const float*)d_in[0];
    const int*   stm    = (const int*)  d_in[1];
    const int*   nstm   = (const int*)  d_in[2];
    const float* ft_w   = (const float*)d_in[3];
    const float* ft_b   = (const float*)d_in[4];
    const float* fft_w  = (const float*)d_in[5];
    const float* fft_b  = (const float*)d_in[6];
    const float* out_w  = (const float*)d_in[7];
    const float* out_b  = (const float*)d_in[8];
    float* out = (float*)d_out;

    // Stage 1: combined e4m3 table (2 rows per warp, 16 rows per block).
    build_table_kernel<<<NUM_FT / 16, 256>>>(ft_w, fft_w);

    // Stage 2: gather + MLP.
    const int batch  = in_sizes[0] / MAXF;   // 8192
    const int blocks = (batch + 3) / 4;
    nnue_halfkp_kernel<<<blocks, 256>>>(values, stm, nstm, ft_b,
                                        fft_b, out_w, out_b, out, batch);
}

// round 14
// speedup vs baseline: 1.3282x; 1.3282x over previous
#include <cuda_runtime.h>
#include <cuda_fp16.h>
#include <cuda_fp8.h>

// NNUE HalfKP forward, e4m3 combined-table (R12 layout + occupancy push).
//
// Stage 1: comb[i][d] = ft_w[i][d] + fft_w[i%640][d]; per-row absmax ->
//   scale (rowmax -> 448); e4m3 encode. 2 rows per warp, loads hoisted.
// Stage 2: gather. Two warps per batch element (warp parity = side).
//   One warp covers ONE contiguous 256B row per feature (warp-coherent --
//   the R13 two-rows-per-LDG split doubled L1 wavefronts and regressed).
//   Batch-4 prefetch + __launch_bounds__(256,8) to force 32 regs -> 8
//   blocks/SM for latency hiding. fp16 accumulate, fp32 epilogue.

constexpr int FT_OUT  = 256;
constexpr int NUM_FT  = 40960;
constexpr int NUM_FFT = 640;
constexpr int MAXF    = 32;

__device__ uint2 g_comb [(size_t)NUM_FT * 32];   // 10 MB e4m3, 8B per lane-chunk
__device__ float g_scale[NUM_FT];                // per-row dequant scale (m/448)

__device__ __forceinline__ __half2 dec_e4m3x2(unsigned int s) {
    __half2_raw r = __nv_cvt_fp8x2_to_halfraw2((__nv_fp8x2_storage_t)(unsigned short)s, __NV_E4M3);
    return __half2(r);
}

__global__ __launch_bounds__(256) void build_table_kernel(
    const float* __restrict__ ft_w,   // [40960, 256]
    const float* __restrict__ fft_w)  // [640, 256]
{
    const int warp = threadIdx.x >> 5;
    const int lane = threadIdx.x & 31;
    const int row0 = (blockIdx.x * 8 + warp) * 2;

    float4 A[2][2], B[2][2];
#pragma unroll
    for (int r = 0; r < 2; ++r) {
        const int row = row0 + r;
        const float* pf = ft_w  + (size_t)row * FT_OUT + lane * 8;
        const float* pg = fft_w + (size_t)(row % NUM_FFT) * FT_OUT + lane * 8;
        A[r][0] = *reinterpret_cast<const float4*>(pf);
        A[r][1] = *reinterpret_cast<const float4*>(pf + 4);
        B[r][0] = *reinterpret_cast<const float4*>(pg);
        B[r][1] = *reinterpret_cast<const float4*>(pg + 4);
    }

#pragma unroll
    for (int r = 0; r < 2; ++r) {
        const int row = row0 + r;
        float s[8] = { A[r][0].x + B[r][0].x, A[r][0].y + B[r][0].y,
                       A[r][0].z + B[r][0].z, A[r][0].w + B[r][0].w,
                       A[r][1].x + B[r][1].x, A[r][1].y + B[r][1].y,
                       A[r][1].z + B[r][1].z, A[r][1].w + B[r][1].w };

        float m = 0.f;
#pragma unroll
        for (int j = 0; j < 8; ++j) m = fmaxf(m, fabsf(s[j]));
#pragma unroll
        for (int off = 16; off > 0; off >>= 1)
            m = fmaxf(m, __shfl_xor_sync(0xffffffffu, m, off));

        m = fmaxf(m, 1e-20f);
        const float inv = 448.0f / m;

        unsigned short e[4];
#pragma unroll
        for (int j = 0; j < 4; ++j) {
            float2 pr = make_float2(s[2 * j] * inv, s[2 * j + 1] * inv);
            e[j] = (unsigned short)__nv_cvt_float2_to_fp8x2(pr, __NV_SATFINITE, __NV_E4M3);
        }
        uint2 packed;
        packed.x = (unsigned)e[0] | ((unsigned)e[1] << 16);
        packed.y = (unsigned)e[2] | ((unsigned)e[3] << 16);

        g_comb[(size_t)row * 32 + lane] = packed;
        if (lane == 0) g_scale[row] = m * (1.0f / 448.0f);
    }
}

__global__ __launch_bounds__(256, 8) void nnue_halfkp_kernel(
    const float* __restrict__ values,        // [B, 32]
    const int*   __restrict__ stm_indices,   // [B, 32]
    const int*   __restrict__ nstm_indices,  // [B, 32]
    const float* __restrict__ ft_b,          // [256]
    const float* __restrict__ fft_b,         // [256]
    const float* __restrict__ out_w,         // [1, 512]
    const float* __restrict__ out_b,         // [1]
    float*       __restrict__ out,           // [B, 1]
    int batch)
{
    __shared__ float s_dot[8];
    __shared__ uint2 s_pre[8][32];            // per-warp: {row index, vsh bits}

    const int warp = threadIdx.x >> 5;        // 0..7
    const int lane = threadIdx.x & 31;
    const int elem = blockIdx.x * 4 + (warp >> 1);
    const int side = warp & 1;                 // 0 = stm, 1 = nstm
    const int e    = (elem < batch) ? elem : (batch - 1);

    const int* __restrict__ idx = side ? nstm_indices : stm_indices;

    // Preload: lane l prepares feature l -> {row index, value*scale fp16x2}.
    {
        const float v = values[e * MAXF + lane];
        const int   i = idx[e * MAXF + lane];
        const float vs = v * g_scale[i];
        const __half2 vsh = __float2half2_rn(vs);
        uint2 t;
        t.x = (unsigned)i;
        t.y = *reinterpret_cast<const unsigned*>(&vsh);
        s_pre[warp][lane] = t;
    }
    __syncwarp();

    // This lane's chunk base; address = lane_base + i*32 (uint2 units).
    const uint2* __restrict__ lane_base = g_comb + lane;

    __half2 acc0 = __float2half2_rn(0.f);
    __half2 acc1 = __float2half2_rn(0.f);
    __half2 acc2 = __float2half2_rn(0.f);
    __half2 acc3 = __float2half2_rn(0.f);

#pragma unroll
    for (int f0 = 0; f0 < MAXF; f0 += 4) {
        // Phase 1: issue 4 independent gathers (and their vsh) up front.
        uint2   p[4];
        __half2 v[4];
#pragma unroll
        for (int j = 0; j < 4; ++j) {
            const uint2 t = s_pre[warp][f0 + j];        // LDS.64 broadcast
            p[j] = lane_base[(size_t)t.x * 32];         // IMAD.WIDE + LDG.64
            v[j] = *reinterpret_cast<const __half2*>(&t.y);
        }
        // Phase 2: decode + accumulate.
#pragma unroll
        for (int j = 0; j < 4; ++j) {
            acc0 = __hfma2(dec_e4m3x2(p[j].x),       v[j], acc0);
            acc1 = __hfma2(dec_e4m3x2(p[j].x >> 16), v[j], acc1);
            acc2 = __hfma2(dec_e4m3x2(p[j].y),       v[j], acc2);
            acc3 = __hfma2(dec_e4m3x2(p[j].y >> 16), v[j], acc3);
        }
    }

    const int col = lane * 8;

    const float2 f0 = __half22float2(acc0);
    const float2 f1 = __half22float2(acc1);
    const float2 f2 = __half22float2(acc2);
    const float2 f3 = __half22float2(acc3);
    const float av[8] = { f0.x, f0.y, f1.x, f1.y, f2.x, f2.y, f3.x, f3.y };

    // Epilogue: exact fp32 biases, clip [0,1], dot with this side's out_w.
    const float4 fb0  = *reinterpret_cast<const float4*>(ft_b  + col);
    const float4 fb1  = *reinterpret_cast<const float4*>(ft_b  + col + 4);
    const float4 ffb0 = *reinterpret_cast<const float4*>(fft_b + col);
    const float4 ffb1 = *reinterpret_cast<const float4*>(fft_b + col + 4);
    const float* w    = out_w + side * FT_OUT;
    const float4 w0   = *reinterpret_cast<const float4*>(w + col);
    const float4 w1   = *reinterpret_cast<const float4*>(w + col + 4);

    const float bias[8] = { fb0.x + ffb0.x, fb0.y + ffb0.y, fb0.z + ffb0.z, fb0.w + ffb0.w,
                            fb1.x + ffb1.x, fb1.y + ffb1.y, fb1.z + ffb1.z, fb1.w + ffb1.w };
    const float wd[8]   = { w0.x, w0.y, w0.z, w0.w, w1.x, w1.y, w1.z, w1.w };

    float dot = 0.f;
#pragma unroll
    for (int j = 0; j < 8; ++j) {
        const float h = fminf(fmaxf(av[j] + bias[j], 0.f), 1.f);
        dot += h * wd[j];
    }

#pragma unroll
    for (int off = 16; off > 0; off >>= 1)
        dot += __shfl_xor_sync(0xffffffffu, dot, off);

    if (lane == 0) s_dot[warp] = dot;
    __syncthreads();

    if (threadIdx.x < 4) {
        const int eo = blockIdx.x * 4 + threadIdx.x;
        if (eo < batch) {
            const float x = s_dot[2 * threadIdx.x] + s_dot[2 * threadIdx.x + 1] + out_b[0];
            out[eo] = 1.0f / (1.0f + expf(-x));
        }
    }
}

extern "C" void kernel_launch(void* const* d_in, const int* in_sizes, int n_in,
                              void* d_out, int out_size)
{
    const float* values = (const float*)d_in[0];
    const int*   stm    = (const int*)  d_in[1];
    const int*   nstm   = (const int*)  d_in[2];
    const float* ft_w   = (const float*)d_in[3];
    const float* ft_b   = (const float*)d_in[4];
    const float* fft_w  = (const float*)d_in[5];
    const float* fft_b  = (const float*)d_in[6];
    const float* out_w  = (const float*)d_in[7];
    const float* out_b  = (const float*)d_in[8];
    float* out = (float*)d_out;

    // Stage 1: combined e4m3 table (2 rows per warp, 16 rows per block).
    build_table_kernel<<<NUM_FT / 16, 256>>>(ft_w, fft_w);

    // Stage 2: gather + MLP.
    const int batch  = in_sizes[0] / MAXF;   // 8192
    const int blocks = (batch + 3) / 4;
    nnue_halfkp_kernel<<<blocks, 256>>>(values, stm, nstm, ft_b,
                                        fft_b, out_w, out_b, out, batch);
}

// round 15
// speedup vs baseline: 1.4444x; 1.0875x over previous
#include <cuda_runtime.h>
#include <cuda_fp16.h>
#include <cuda_fp8.h>

// NNUE HalfKP forward, e4m3 combined-table.
//
// Stage 1: comb[i][d] = ft_w[i][d] + fft_w[i%640][d]; per-row absmax ->
//   scale (rowmax -> 448); e4m3 encode. 2 rows per warp, 8 LDG.128
//   hoisted; row absmax via single REDUX (__reduce_max_sync on fabs bits,
//   order-preserving for non-negative floats) instead of a 5-step
//   shfl+fmax dependency chain.
// Stage 2: gather (unchanged from best). Two warps per batch element
//   (warp parity = side); one warp covers ONE contiguous 256B row per
//   feature; batch-4 prefetch; __launch_bounds__(256,8) -> 32 regs,
//   8 blocks/SM. fp16 accumulate, fp32 epilogue with exact fp32 biases.

constexpr int FT_OUT  = 256;
constexpr int NUM_FT  = 40960;
constexpr int NUM_FFT = 640;
constexpr int MAXF    = 32;

__device__ uint2 g_comb [(size_t)NUM_FT * 32];   // 10 MB e4m3, 8B per lane-chunk
__device__ float g_scale[NUM_FT];                // per-row dequant scale (m/448)

__device__ __forceinline__ __half2 dec_e4m3x2(unsigned int s) {
    __half2_raw r = __nv_cvt_fp8x2_to_halfraw2((__nv_fp8x2_storage_t)(unsigned short)s, __NV_E4M3);
    return __half2(r);
}

__global__ __launch_bounds__(256) void build_table_kernel(
    const float* __restrict__ ft_w,   // [40960, 256]
    const float* __restrict__ fft_w)  // [640, 256]
{
    const int warp = threadIdx.x >> 5;
    const int lane = threadIdx.x & 31;
    const int row0 = (blockIdx.x * 8 + warp) * 2;

    // Hoist all 8 LDG.128 (2 rows x 4 vectors) for MLP on the 42MB stream.
    float4 A[2][2], B[2][2];
#pragma unroll
    for (int r = 0; r < 2; ++r) {
        const int row = row0 + r;
        const float* pf = ft_w  + (size_t)row * FT_OUT + lane * 8;
        const float* pg = fft_w + (size_t)(row % NUM_FFT) * FT_OUT + lane * 8;
        A[r][0] = *reinterpret_cast<const float4*>(pf);
        A[r][1] = *reinterpret_cast<const float4*>(pf + 4);
        B[r][0] = *reinterpret_cast<const float4*>(pg);
        B[r][1] = *reinterpret_cast<const float4*>(pg + 4);
    }

    // Sums + per-lane absmax for both rows (independent -> ILP).
    float s[2][8];
    unsigned int mb[2];
#pragma unroll
    for (int r = 0; r < 2; ++r) {
        s[r][0] = A[r][0].x + B[r][0].x;  s[r][1] = A[r][0].y + B[r][0].y;
        s[r][2] = A[r][0].z + B[r][0].z;  s[r][3] = A[r][0].w + B[r][0].w;
        s[r][4] = A[r][1].x + B[r][1].x;  s[r][5] = A[r][1].y + B[r][1].y;
        s[r][6] = A[r][1].z + B[r][1].z;  s[r][7] = A[r][1].w + B[r][1].w;
        float m = 0.f;
#pragma unroll
        for (int j = 0; j < 8; ++j) m = fmaxf(m, fabsf(s[r][j]));
        mb[r] = __float_as_uint(m);   // non-negative float: uint order == float order
    }

    // One REDUX per row replaces the 5-step shfl chain.
    mb[0] = __reduce_max_sync(0xffffffffu, mb[0]);
    mb[1] = __reduce_max_sync(0xffffffffu, mb[1]);

#pragma unroll
    for (int r = 0; r < 2; ++r) {
        const int row = row0 + r;
        const float m = fmaxf(__uint_as_float(mb[r]), 1e-20f);
        const float inv = 448.0f / m;

        unsigned short e[4];
#pragma unroll
        for (int j = 0; j < 4; ++j) {
            float2 pr = make_float2(s[r][2 * j] * inv, s[r][2 * j + 1] * inv);
            e[j] = (unsigned short)__nv_cvt_float2_to_fp8x2(pr, __NV_SATFINITE, __NV_E4M3);
        }
        uint2 packed;
        packed.x = (unsigned)e[0] | ((unsigned)e[1] << 16);
        packed.y = (unsigned)e[2] | ((unsigned)e[3] << 16);

        g_comb[(size_t)row * 32 + lane] = packed;
        if (lane == 0) g_scale[row] = m * (1.0f / 448.0f);
    }
}

__global__ __launch_bounds__(256, 8) void nnue_halfkp_kernel(
    const float* __restrict__ values,        // [B, 32]
    const int*   __restrict__ stm_indices,   // [B, 32]
    const int*   __restrict__ nstm_indices,  // [B, 32]
    const float* __restrict__ ft_b,          // [256]
    const float* __restrict__ fft_b,         // [256]
    const float* __restrict__ out_w,         // [1, 512]
    const float* __restrict__ out_b,         // [1]
    float*       __restrict__ out,           // [B, 1]
    int batch)
{
    __shared__ float s_dot[8];
    __shared__ uint2 s_pre[8][32];            // per-warp: {row index, vsh bits}

    const int warp = threadIdx.x >> 5;        // 0..7
    const int lane = threadIdx.x & 31;
    const int elem = blockIdx.x * 4 + (warp >> 1);
    const int side = warp & 1;                 // 0 = stm, 1 = nstm
    const int e    = (elem < batch) ? elem : (batch - 1);

    const int* __restrict__ idx = side ? nstm_indices : stm_indices;

    // Preload: lane l prepares feature l -> {row index, value*scale fp16x2}.
    {
        const float v = values[e * MAXF + lane];
        const int   i = idx[e * MAXF + lane];
        const float vs = v * g_scale[i];
        const __half2 vsh = __float2half2_rn(vs);
        uint2 t;
        t.x = (unsigned)i;
        t.y = *reinterpret_cast<const unsigned*>(&vsh);
        s_pre[warp][lane] = t;
    }
    __syncwarp();

    // This lane's chunk base; address = lane_base + i*32 (uint2 units).
    const uint2* __restrict__ lane_base = g_comb + lane;

    __half2 acc0 = __float2half2_rn(0.f);
    __half2 acc1 = __float2half2_rn(0.f);
    __half2 acc2 = __float2half2_rn(0.f);
    __half2 acc3 = __float2half2_rn(0.f);

#pragma unroll
    for (int f0 = 0; f0 < MAXF; f0 += 4) {
        // Phase 1: issue 4 independent gathers (and their vsh) up front.
        uint2   p[4];
        __half2 v[4];
#pragma unroll
        for (int j = 0; j < 4; ++j) {
            const uint2 t = s_pre[warp][f0 + j];        // LDS.64 broadcast
            p[j] = lane_base[(size_t)t.x * 32];         // IMAD.WIDE + LDG.64
            v[j] = *reinterpret_cast<const __half2*>(&t.y);
        }
        // Phase 2: decode + accumulate.
#pragma unroll
        for (int j = 0; j < 4; ++j) {
            acc0 = __hfma2(dec_e4m3x2(p[j].x),       v[j], acc0);
            acc1 = __hfma2(dec_e4m3x2(p[j].x >> 16), v[j], acc1);
            acc2 = __hfma2(dec_e4m3x2(p[j].y),       v[j], acc2);
            acc3 = __hfma2(dec_e4m3x2(p[j].y >> 16), v[j], acc3);
        }
    }

    const int col = lane * 8;

    const float2 f0 = __half22float2(acc0);
    const float2 f1 = __half22float2(acc1);
    const float2 f2 = __half22float2(acc2);
    const float2 f3 = __half22float2(acc3);
    const float av[8] = { f0.x, f0.y, f1.x, f1.y, f2.x, f2.y, f3.x, f3.y };

    // Epilogue: exact fp32 biases, clip [0,1], dot with this side's out_w.
    const float4 fb0  = *reinterpret_cast<const float4*>(ft_b  + col);
    const float4 fb1  = *reinterpret_cast<const float4*>(ft_b  + col + 4);
    const float4 ffb0 = *reinterpret_cast<const float4*>(fft_b + col);
    const float4 ffb1 = *reinterpret_cast<const float4*>(fft_b + col + 4);
    const float* w    = out_w + side * FT_OUT;
    const float4 w0   = *reinterpret_cast<const float4*>(w + col);
    const float4 w1   = *reinterpret_cast<const float4*>(w + col + 4);

    const float bias[8] = { fb0.x + ffb0.x, fb0.y + ffb0.y, fb0.z + ffb0.z, fb0.w + ffb0.w,
                            fb1.x + ffb1.x, fb1.y + ffb1.y, fb1.z + ffb1.z, fb1.w + ffb1.w };
    const float wd[8]   = { w0.x, w0.y, w0.z, w0.w, w1.x, w1.y, w1.z, w1.w };

    float dot = 0.f;
#pragma unroll
    for (int j = 0; j < 8; ++j) {
        const float h = fminf(fmaxf(av[j] + bias[j], 0.f), 1.f);
        dot += h * wd[j];
    }

#pragma unroll
    for (int off = 16; off > 0; off >>= 1)
        dot += __shfl_xor_sync(0xffffffffu, dot, off);

    if (lane == 0) s_dot[warp] = dot;
    __syncthreads();

    if (threadIdx.x < 4) {
        const int eo = blockIdx.x * 4 + threadIdx.x;
        if (eo < batch) {
            const float x = s_dot[2 * threadIdx.x] + s_dot[2 * threadIdx.x + 1] + out_b[0];
            out[eo] = 1.0f / (1.0f + expf(-x));
        }
    }
}

extern "C" void kernel_launch(void* const* d_in, const int* in_sizes, int n_in,
                              void* d_out, int out_size)
{
    const float* values = (const float*)d_in[0];
    const int*   stm    = (const int*)  d_in[1];
    const int*   nstm   = (const int*)  d_in[2];
    const float* ft_w   = (const float*)d_in[3];
    const float* ft_b   = (const float*)d_in[4];
    const float* fft_w  = (const float*)d_in[5];
    const float* fft_b  = (const float*)d_in[6];
    const float* out_w  = (const float*)d_in[7];
    const float* out_b  = (const float*)d_in[8];
    float* out = (float*)d_out;

    // Stage 1: combined e4m3 table (2 rows per warp, 16 rows per block).
    build_table_kernel<<<NUM_FT / 16, 256>>>(ft_w, fft_w);

    // Stage 2: gather + MLP.
    const int batch  = in_sizes[0] / MAXF;   // 8192
    const int blocks = (batch + 3) / 4;
    nnue_halfkp_kernel<<<blocks, 256>>>(values, stm, nstm, ft_b,
                                        fft_b, out_w, out_b, out, batch);
}